// round 6
// baseline (speedup 1.0000x reference)
#include <cuda_runtime.h>

// Controlled-SX on qutrits (dim=3, 16 qudits), ctrl=2, obj=5.
//   d2!=1          : out[i] = in[i]
//   d2==1, d5==0   : out[i] = in[i + 3^10]
//   d2==1, d5==1   : out[i] = in[i - 3^10]
//   d2==1, d5==2   : out[i] = 0
// Grid-stride persistent form: 1184 CTAs (148 SM x 8), each loops over quads
// with stride gridDim*blockDim -> perfect coalescing preserved, block-launch
// overhead amortized, cross-iteration ILP.
// Kernel is at the measured DRAM roofline (~6.95 TB/s app traffic); this
// round targets launch/tail overhead only.
// out_im = d_out + n with n odd -> 4B-aligned only: scalar stores for im.

static constexpr int S5 = 59049;    // 3^10
static constexpr int S2 = 1594323;  // 3^13 = 27 * S5

__device__ __forceinline__ void scalar_one(const float* __restrict__ in_re,
                                           const float* __restrict__ in_im,
                                           float* __restrict__ out_re,
                                           float* __restrict__ out_im,
                                           int idx)
{
    int q5 = idx / S5;
    int d5 = q5 % 3;
    int d2 = (q5 / 27) % 3;
    float vr, vi;
    if (d2 != 1) {
        vr = __ldg(in_re + idx);
        vi = __ldg(in_im + idx);
    } else if (d5 == 0) {
        vr = __ldg(in_re + idx + S5);
        vi = __ldg(in_im + idx + S5);
    } else if (d5 == 1) {
        vr = __ldg(in_re + idx - S5);
        vi = __ldg(in_im + idx - S5);
    } else {
        vr = 0.0f; vi = 0.0f;
    }
    out_re[idx] = vr;
    out_im[idx] = vi;
}

__device__ __forceinline__ void do_quad(const float* __restrict__ in_re,
                                        const float* __restrict__ in_im,
                                        float* __restrict__ out_re,
                                        float* __restrict__ out_im,
                                        int n, int q)
{
    int i = q << 2;

    int q5 = i / S5;                 // magic-mul divide
    int r5 = i - q5 * S5;
    int d5 = q5 % 3;
    int d2 = (q5 / 27) % 3;

    bool fast = (i + 4 <= n) && (r5 + 4 <= S5);

    if (fast) {
        const float4* in_re4  = reinterpret_cast<const float4*>(in_re);
        const float4* in_im4  = reinterpret_cast<const float4*>(in_im);
        float4*       out_re4 = reinterpret_cast<float4*>(out_re);

        float4 vr, vi;
        if (d2 != 1) {
            vr = __ldg(in_re4 + q);          // LDG.128, fully coalesced
            vi = __ldg(in_im4 + q);
        } else if (d5 == 2) {
            vr = make_float4(0.f, 0.f, 0.f, 0.f);
            vi = vr;
        } else {
            int s = (d5 == 0) ? (i + S5) : (i - S5);  // odd offset: scalar gather
            vr.x = __ldg(in_re + s + 0);
            vr.y = __ldg(in_re + s + 1);
            vr.z = __ldg(in_re + s + 2);
            vr.w = __ldg(in_re + s + 3);
            vi.x = __ldg(in_im + s + 0);
            vi.y = __ldg(in_im + s + 1);
            vi.z = __ldg(in_im + s + 2);
            vi.w = __ldg(in_im + s + 3);
        }
        out_re4[q] = vr;                     // STG.128 (aligned)
        out_im[i + 0] = vi.x;                // STG.32 x4 (out_im 4B-aligned only)
        out_im[i + 1] = vi.y;
        out_im[i + 2] = vi.z;
        out_im[i + 3] = vi.w;
    } else {
        #pragma unroll
        for (int j = 0; j < 4; j++) {
            int idx = i + j;
            if (idx < n)
                scalar_one(in_re, in_im, out_re, out_im, idx);
        }
    }
}

__global__ void __launch_bounds__(256)
sx_apply_gs(const float* __restrict__ in_re,
            const float* __restrict__ in_im,
            float* __restrict__ out_re,
            float* __restrict__ out_im,
            int n, int nq)
{
    const int stride = gridDim.x * blockDim.x;
    for (int q = blockIdx.x * blockDim.x + threadIdx.x; q < nq; q += stride)
        do_quad(in_re, in_im, out_re, out_im, n, q);
}

extern "C" void kernel_launch(void* const* d_in, const int* in_sizes, int n_in,
                              void* d_out, int out_size)
{
    const float* in_re = (const float*)d_in[0];
    const float* in_im = (const float*)d_in[1];
    const int n = in_sizes[0];          // 3^16 = 43,046,721 (odd)

    float* out_re = (float*)d_out;
    float* out_im = (float*)d_out + n;  // 4B-aligned only

    const int nq = (n + 3) >> 2;
    const int threads = 256;
    const int blocks = 148 * 8;          // persistent-style: 8 CTAs per SM
    sx_apply_gs<<<blocks, threads>>>(in_re, in_im, out_re, out_im, n, nq);
}

// round 7
// speedup vs baseline: 1.2733x; 1.2733x over previous
#include <cuda_runtime.h>

// Controlled-SX on qutrits (dim=3, 16 qudits), ctrl=2, obj=5.
//   d2!=1          : out[i] = in[i]
//   d2==1, d5==0   : out[i] = in[i + 3^10]
//   d2==1, d5==1   : out[i] = in[i - 3^10]
//   d2==1, d5==2   : out[i] = 0
// Flat launch, 1 thread = 1 quad (R3 structure — best measured; R6 showed
// grid-stride loops regress on this kernel). Streaming cache hints:
// __ldcs / __stcs — data is never re-read, keep it out of L2 residency.
// out_im = d_out + n with n odd -> 4B-aligned only: scalar stores for im.

static constexpr int S5 = 59049;    // 3^10
static constexpr int S2 = 1594323;  // 3^13 = 27 * S5

__device__ __forceinline__ void scalar_one(const float* __restrict__ in_re,
                                           const float* __restrict__ in_im,
                                           float* __restrict__ out_re,
                                           float* __restrict__ out_im,
                                           int idx)
{
    int q5 = idx / S5;
    int d5 = q5 % 3;
    int d2 = (q5 / 27) % 3;
    float vr, vi;
    if (d2 != 1) {
        vr = __ldcs(in_re + idx);
        vi = __ldcs(in_im + idx);
    } else if (d5 == 0) {
        vr = __ldcs(in_re + idx + S5);
        vi = __ldcs(in_im + idx + S5);
    } else if (d5 == 1) {
        vr = __ldcs(in_re + idx - S5);
        vi = __ldcs(in_im + idx - S5);
    } else {
        vr = 0.0f; vi = 0.0f;
    }
    __stcs(out_re + idx, vr);
    __stcs(out_im + idx, vi);
}

__global__ void __launch_bounds__(256)
sx_apply_v4s(const float* __restrict__ in_re,
             const float* __restrict__ in_im,
             float* __restrict__ out_re,
             float* __restrict__ out_im,   // 4B-aligned only: scalar stores
             int n, int nq)
{
    int q = blockIdx.x * blockDim.x + threadIdx.x;
    if (q >= nq) return;
    int i = q << 2;

    int q5 = i / S5;                 // magic-mul divide
    int r5 = i - q5 * S5;
    int d5 = q5 % 3;
    int d2 = (q5 / 27) % 3;

    bool fast = (i + 4 <= n) && (r5 + 4 <= S5);

    if (fast) {
        const float4* in_re4  = reinterpret_cast<const float4*>(in_re);
        const float4* in_im4  = reinterpret_cast<const float4*>(in_im);
        float4*       out_re4 = reinterpret_cast<float4*>(out_re);

        float4 vr, vi;
        if (d2 != 1) {
            vr = __ldcs(in_re4 + q);         // LDG.E.128.STRM
            vi = __ldcs(in_im4 + q);
        } else if (d5 == 2) {
            vr = make_float4(0.f, 0.f, 0.f, 0.f);
            vi = vr;
        } else {
            int s = (d5 == 0) ? (i + S5) : (i - S5);  // odd offset: scalar gather
            vr.x = __ldcs(in_re + s + 0);
            vr.y = __ldcs(in_re + s + 1);
            vr.z = __ldcs(in_re + s + 2);
            vr.w = __ldcs(in_re + s + 3);
            vi.x = __ldcs(in_im + s + 0);
            vi.y = __ldcs(in_im + s + 1);
            vi.z = __ldcs(in_im + s + 2);
            vi.w = __ldcs(in_im + s + 3);
        }
        __stcs(out_re4 + q, vr);             // STG.128 streaming (aligned)
        __stcs(out_im + i + 0, vi.x);        // STG.32 streaming x4
        __stcs(out_im + i + 1, vi.y);
        __stcs(out_im + i + 2, vi.z);
        __stcs(out_im + i + 3, vi.w);
    } else {
        #pragma unroll
        for (int j = 0; j < 4; j++) {
            int idx = i + j;
            if (idx < n)
                scalar_one(in_re, in_im, out_re, out_im, idx);
        }
    }
}

extern "C" void kernel_launch(void* const* d_in, const int* in_sizes, int n_in,
                              void* d_out, int out_size)
{
    const float* in_re = (const float*)d_in[0];
    const float* in_im = (const float*)d_in[1];
    const int n = in_sizes[0];          // 3^16 = 43,046,721 (odd)

    float* out_re = (float*)d_out;
    float* out_im = (float*)d_out + n;  // 4B-aligned only

    const int nq = (n + 3) >> 2;
    const int threads = 256;
    const int blocks = (nq + threads - 1) / threads;
    sx_apply_v4s<<<blocks, threads>>>(in_re, in_im, out_re, out_im, n, nq);
}

// round 8
// speedup vs baseline: 1.2821x; 1.0069x over previous
#include <cuda_runtime.h>

// Controlled-SX on qutrits (dim=3, 16 qudits), ctrl=2, obj=5.
//   d2!=1          : out[i] = in[i]
//   d2==1, d5==0   : out[i] = in[i + 3^10]
//   d2==1, d5==1   : out[i] = in[i - 3^10]
//   d2==1, d5==2   : out[i] = 0
// Flat launch, 1 thread = 1 quad (best structure; R4 consecutive-quads and
// R6 grid-stride both regressed). Streaming hints kept. 512-thread blocks
// to halve block count / trim wave-quantization tail.
// Ceiling evidence: R3/R5/R7 all plateau at ~6.38 TB/s -> DRAM-bound final.
// out_im = d_out + n with n odd -> 4B-aligned only: scalar stores for im.

static constexpr int S5 = 59049;    // 3^10
static constexpr int S2 = 1594323;  // 3^13 = 27 * S5

__device__ __forceinline__ void scalar_one(const float* __restrict__ in_re,
                                           const float* __restrict__ in_im,
                                           float* __restrict__ out_re,
                                           float* __restrict__ out_im,
                                           int idx)
{
    int q5 = idx / S5;
    int d5 = q5 % 3;
    int d2 = (q5 / 27) % 3;
    float vr, vi;
    if (d2 != 1) {
        vr = __ldcs(in_re + idx);
        vi = __ldcs(in_im + idx);
    } else if (d5 == 0) {
        vr = __ldcs(in_re + idx + S5);
        vi = __ldcs(in_im + idx + S5);
    } else if (d5 == 1) {
        vr = __ldcs(in_re + idx - S5);
        vi = __ldcs(in_im + idx - S5);
    } else {
        vr = 0.0f; vi = 0.0f;
    }
    __stcs(out_re + idx, vr);
    __stcs(out_im + idx, vi);
}

__global__ void __launch_bounds__(512)
sx_apply_v4w(const float* __restrict__ in_re,
             const float* __restrict__ in_im,
             float* __restrict__ out_re,
             float* __restrict__ out_im,   // 4B-aligned only: scalar stores
             int n, int nq)
{
    int q = blockIdx.x * blockDim.x + threadIdx.x;
    if (q >= nq) return;
    int i = q << 2;

    int q5 = i / S5;                 // magic-mul divide
    int r5 = i - q5 * S5;
    int d5 = q5 % 3;
    int d2 = (q5 / 27) % 3;

    bool fast = (i + 4 <= n) && (r5 + 4 <= S5);

    if (fast) {
        const float4* in_re4  = reinterpret_cast<const float4*>(in_re);
        const float4* in_im4  = reinterpret_cast<const float4*>(in_im);
        float4*       out_re4 = reinterpret_cast<float4*>(out_re);

        float4 vr, vi;
        if (d2 != 1) {
            vr = __ldcs(in_re4 + q);         // LDG.E.128 streaming, coalesced
            vi = __ldcs(in_im4 + q);
        } else if (d5 == 2) {
            vr = make_float4(0.f, 0.f, 0.f, 0.f);
            vi = vr;
        } else {
            int s = (d5 == 0) ? (i + S5) : (i - S5);  // odd offset: scalar gather
            vr.x = __ldcs(in_re + s + 0);
            vr.y = __ldcs(in_re + s + 1);
            vr.z = __ldcs(in_re + s + 2);
            vr.w = __ldcs(in_re + s + 3);
            vi.x = __ldcs(in_im + s + 0);
            vi.y = __ldcs(in_im + s + 1);
            vi.z = __ldcs(in_im + s + 2);
            vi.w = __ldcs(in_im + s + 3);
        }
        __stcs(out_re4 + q, vr);             // STG.128 streaming (aligned)
        __stcs(out_im + i + 0, vi.x);        // STG.32 streaming x4
        __stcs(out_im + i + 1, vi.y);
        __stcs(out_im + i + 2, vi.z);
        __stcs(out_im + i + 3, vi.w);
    } else {
        #pragma unroll
        for (int j = 0; j < 4; j++) {
            int idx = i + j;
            if (idx < n)
                scalar_one(in_re, in_im, out_re, out_im, idx);
        }
    }
}

extern "C" void kernel_launch(void* const* d_in, const int* in_sizes, int n_in,
                              void* d_out, int out_size)
{
    const float* in_re = (const float*)d_in[0];
    const float* in_im = (const float*)d_in[1];
    const int n = in_sizes[0];          // 3^16 = 43,046,721 (odd)

    float* out_re = (float*)d_out;
    float* out_im = (float*)d_out + n;  // 4B-aligned only

    const int nq = (n + 3) >> 2;
    const int threads = 512;
    const int blocks = (nq + threads - 1) / threads;
    sx_apply_v4w<<<blocks, threads>>>(in_re, in_im, out_re, out_im, n, nq);
}